// round 1
// baseline (speedup 1.0000x reference)
#include <cuda_runtime.h>

#define M_TOTAL 2048
#define IN_DIM  4096
#define OUT_DIM 4096
#define NB      16     // blocks per dim
#define RANK    16
#define BLK     256    // block size

// Scratch (allocation-free rule: __device__ globals)
__device__ float g_T[M_TOTAL * NB * RANK];   // [m][i][r]  2 MB
__device__ float g_rsp[M_TOTAL * NB];        // rowsum partials [m][i]

// ---------------- Kernel A: T[m,i,r] = sum_p x[m, i*256+p] * Vt[i,p,r] ----------------
#define ROWS_A  64
#define XSTRIDE 260   // 256 + 4 pad, float4-aligned, conflict-free banks

__global__ void __launch_bounds__(256)
kernelA(const float* __restrict__ x, const float* __restrict__ Vt)
{
    extern __shared__ float sm[];
    float* xs  = sm;                        // ROWS_A * XSTRIDE
    float* vts = sm + ROWS_A * XSTRIDE;     // 256*16 = 4096 floats

    const int i    = blockIdx.x;
    const int row0 = blockIdx.y * ROWS_A;
    const int tid  = threadIdx.x;

    // Load Vt block i (4096 floats) into smem
    const float4* Vt4  = (const float4*)(Vt + (size_t)i * (BLK * RANK));
    float4*       vts4 = (float4*)vts;
    #pragma unroll
    for (int idx = tid; idx < 1024; idx += 256) vts4[idx] = Vt4[idx];

    // Load 64 rows of x-block i into smem (coalesced 128B)
    const float4* xg4 = (const float4*)x;
    #pragma unroll
    for (int idx = tid; idx < ROWS_A * 64; idx += 256) {
        int m  = idx >> 6;
        int c4 = idx & 63;
        float4 v = xg4[(size_t)(row0 + m) * (IN_DIM / 4) + i * 64 + c4];
        ((float4*)(xs + m * XSTRIDE))[c4] = v;
    }
    __syncthreads();

    const int mm = tid >> 2;       // row 0..63
    const int rg = tid & 3;        // r-quad: r0 = rg*4
    const float4* xr4 = (const float4*)(xs + mm * XSTRIDE);
    const float4* vt4 = (const float4*)vts;

    float ax = 0.f, ay = 0.f, az = 0.f, aw = 0.f;
    #pragma unroll 4
    for (int p4 = 0; p4 < 64; ++p4) {
        float4 xv = xr4[p4];
        // p = 4*p4 + j ;  float4 index of Vt[p][rg*4] = 16*p4 + 4*j + rg
        float4 v0 = vt4[16 * p4 + rg];
        ax = fmaf(xv.x, v0.x, ax); ay = fmaf(xv.x, v0.y, ay);
        az = fmaf(xv.x, v0.z, az); aw = fmaf(xv.x, v0.w, aw);
        float4 v1 = vt4[16 * p4 + 4 + rg];
        ax = fmaf(xv.y, v1.x, ax); ay = fmaf(xv.y, v1.y, ay);
        az = fmaf(xv.y, v1.z, az); aw = fmaf(xv.y, v1.w, aw);
        float4 v2 = vt4[16 * p4 + 8 + rg];
        ax = fmaf(xv.z, v2.x, ax); ay = fmaf(xv.z, v2.y, ay);
        az = fmaf(xv.z, v2.z, az); aw = fmaf(xv.z, v2.w, aw);
        float4 v3 = vt4[16 * p4 + 12 + rg];
        ax = fmaf(xv.w, v3.x, ax); ay = fmaf(xv.w, v3.y, ay);
        az = fmaf(xv.w, v3.z, az); aw = fmaf(xv.w, v3.w, aw);
    }
    float4 tv = make_float4(ax, ay, az, aw);
    *((float4*)(g_T + (size_t)(row0 + mm) * (NB * RANK) + i * RANK + rg * 4)) = tv;

    // rowsum partial for this input block (deterministic, no atomics)
    if (tid < ROWS_A) {
        const float4* xr = (const float4*)(xs + tid * XSTRIDE);
        float s = 0.f;
        #pragma unroll 8
        for (int c4 = 0; c4 < 64; ++c4) {
            float4 v = xr[c4];
            s += (v.x + v.y) + (v.z + v.w);
        }
        g_rsp[(size_t)(row0 + tid) * NB + i] = s;
    }
}

// ---------------- Kernel B: out = Z @ U + (rowsum+1)*bias ----------------
#define ROWS_B  32
#define TSTRIDE 264   // 256 + 8 pad (float4 aligned, de-conflicted)
#define ZSTRIDE 20    // 16 + 4 pad (float4 aligned)

__global__ void __launch_bounds__(256)
kernelB(const float* __restrict__ S, const float* __restrict__ U,
        const float* __restrict__ bias, float* __restrict__ out)
{
    __shared__ float Ts[ROWS_B * TSTRIDE];
    __shared__ float Zs[ROWS_B * ZSTRIDE];
    __shared__ float rs[ROWS_B];

    const int obase = blockIdx.x * 4;
    const int row0  = blockIdx.y * ROWS_B;
    const int tid   = threadIdx.x;

    // Load T rows for this tile
    const float4* gT4 = (const float4*)g_T;
    #pragma unroll
    for (int idx = tid; idx < ROWS_B * 64; idx += 256) {
        int m  = idx >> 6;
        int c4 = idx & 63;
        ((float4*)(Ts + m * TSTRIDE))[c4] = gT4[(size_t)(row0 + m) * 64 + c4];
    }
    // rowsum (fold the +1 of the bias identity trick)
    if (tid < ROWS_B) {
        float s = 1.0f;
        #pragma unroll
        for (int i = 0; i < NB; ++i) s += g_rsp[(size_t)(row0 + tid) * NB + i];
        rs[tid] = s;
    }
    __syncthreads();

    const int zm = tid >> 3;       // row 0..31
    const int zr = tid & 7;        // r and r+8
    const float* Trow = Ts + zm * TSTRIDE;

    for (int oo = 0; oo < 4; ++oo) {
        const int o = obase + oo;

        // Z[m][r] = sum_i T[m][i][r] * S[o][i][r]   (2 entries per thread)
        const float* Sb = S + o * (NB * RANK);
        float z0 = 0.f, z1 = 0.f;
        #pragma unroll
        for (int i = 0; i < NB; ++i) {
            z0 = fmaf(Trow[i * 16 + zr],     Sb[i * 16 + zr],     z0);
            z1 = fmaf(Trow[i * 16 + zr + 8], Sb[i * 16 + zr + 8], z1);
        }

        // U column q=tid for this output block (L2-hot, coalesced)
        float u[16];
        const float* Ub = U + (size_t)o * (RANK * BLK);
        #pragma unroll
        for (int r = 0; r < 16; ++r) u[r] = Ub[r * 256 + tid];
        const float bq = bias[o * 256 + tid];

        __syncthreads();            // previous iteration's Zs readers done
        Zs[zm * ZSTRIDE + zr]     = z0;
        Zs[zm * ZSTRIDE + zr + 8] = z1;
        __syncthreads();            // Zs ready

        const size_t ob = (size_t)row0 * OUT_DIM + o * 256 + tid;
        #pragma unroll 4
        for (int m = 0; m < ROWS_B; ++m) {
            const float4* zp = (const float4*)(Zs + m * ZSTRIDE);
            float4 za = zp[0], zb = zp[1], zc = zp[2], zd = zp[3];
            float acc = rs[m] * bq;   // (rowsum+1)*bias
            acc = fmaf(za.x, u[0],  acc); acc = fmaf(za.y, u[1],  acc);
            acc = fmaf(za.z, u[2],  acc); acc = fmaf(za.w, u[3],  acc);
            acc = fmaf(zb.x, u[4],  acc); acc = fmaf(zb.y, u[5],  acc);
            acc = fmaf(zb.z, u[6],  acc); acc = fmaf(zb.w, u[7],  acc);
            acc = fmaf(zc.x, u[8],  acc); acc = fmaf(zc.y, u[9],  acc);
            acc = fmaf(zc.z, u[10], acc); acc = fmaf(zc.w, u[11], acc);
            acc = fmaf(zd.x, u[12], acc); acc = fmaf(zd.y, u[13], acc);
            acc = fmaf(zd.z, u[14], acc); acc = fmaf(zd.w, u[15], acc);
            out[ob + (size_t)m * OUT_DIM] = acc;
        }
    }
}

extern "C" void kernel_launch(void* const* d_in, const int* in_sizes, int n_in,
                              void* d_out, int out_size)
{
    const float* x    = (const float*)d_in[0];
    const float* S    = (const float*)d_in[1];
    const float* U    = (const float*)d_in[2];
    const float* Vt   = (const float*)d_in[3];
    const float* bias = (const float*)d_in[4];
    float* out = (float*)d_out;

    const int smA = (ROWS_A * XSTRIDE + BLK * RANK) * (int)sizeof(float);  // 82,944 B
    cudaFuncSetAttribute(kernelA, cudaFuncAttributeMaxDynamicSharedMemorySize, smA);

    kernelA<<<dim3(NB, M_TOTAL / ROWS_A), 256, smA>>>(x, Vt);
    kernelB<<<dim3(4, M_TOTAL / ROWS_B), 256>>>(S, U, bias, out);
}

// round 2
// speedup vs baseline: 1.1050x; 1.1050x over previous
#include <cuda_runtime.h>

#define M_TOTAL 2048
#define IN_DIM  4096
#define OUT_DIM 4096
#define NB      16     // blocks per dim
#define RANK    16
#define BLK     256    // block size

// Scratch (allocation-free rule: __device__ globals)
// Two split-K halves of T: [half][m][i][r]
__device__ float g_T[2 * M_TOTAL * NB * RANK];      // 4 MB
__device__ float g_rsp[M_TOTAL * NB * 2];           // rowsum partials [m][i*2+half]

// ---------------- Kernel A: T_half[m,i,r] = sum_{p in half} x[m, i*256+p] * Vt[i,p,r] ----
#define ROWS_A   64
#define KA       128            // p's per CTA (split-K = 2)
#define XSTRIDE  132            // 128 + 4 pad, float4-aligned, conflict-free

__global__ void __launch_bounds__(256)
kernelA(const float* __restrict__ x, const float* __restrict__ Vt)
{
    __shared__ float xs[ROWS_A * XSTRIDE];   // 33.8 KB
    __shared__ float vts[KA * RANK];         // 8 KB

    const int i    = blockIdx.x >> 1;
    const int half = blockIdx.x & 1;
    const int row0 = blockIdx.y * ROWS_A;
    const int tid  = threadIdx.x;

    // Load Vt half-block (2048 floats = 512 float4)
    const float4* Vt4  = (const float4*)(Vt + (size_t)i * (BLK * RANK) + half * (KA * RANK));
    float4*       vts4 = (float4*)vts;
    #pragma unroll
    for (int idx = tid; idx < 512; idx += 256) vts4[idx] = Vt4[idx];

    // Load 64 rows x 128 cols of x (coalesced 128B)
    const float4* xg4 = (const float4*)x;
    #pragma unroll
    for (int idx = tid; idx < ROWS_A * 32; idx += 256) {
        int m  = idx >> 5;
        int c4 = idx & 31;
        float4 v = xg4[(size_t)(row0 + m) * (IN_DIM / 4) + i * 64 + half * 32 + c4];
        ((float4*)(xs + m * XSTRIDE))[c4] = v;
    }
    __syncthreads();

    const int mm = tid >> 2;       // row 0..63
    const int rg = tid & 3;        // r-quad: r0 = rg*4
    const float4* xr4 = (const float4*)(xs + mm * XSTRIDE);
    const float4* vt4 = (const float4*)vts;

    float ax = 0.f, ay = 0.f, az = 0.f, aw = 0.f;
    float s  = 0.f;                 // rowsum partial (all lanes compute; rg==0 stores)
    #pragma unroll 4
    for (int p4 = 0; p4 < 32; ++p4) {
        float4 xv = xr4[p4];
        float4 v0 = vt4[16 * p4 + rg];
        ax = fmaf(xv.x, v0.x, ax); ay = fmaf(xv.x, v0.y, ay);
        az = fmaf(xv.x, v0.z, az); aw = fmaf(xv.x, v0.w, aw);
        float4 v1 = vt4[16 * p4 + 4 + rg];
        ax = fmaf(xv.y, v1.x, ax); ay = fmaf(xv.y, v1.y, ay);
        az = fmaf(xv.y, v1.z, az); aw = fmaf(xv.y, v1.w, aw);
        float4 v2 = vt4[16 * p4 + 8 + rg];
        ax = fmaf(xv.z, v2.x, ax); ay = fmaf(xv.z, v2.y, ay);
        az = fmaf(xv.z, v2.z, az); aw = fmaf(xv.z, v2.w, aw);
        float4 v3 = vt4[16 * p4 + 12 + rg];
        ax = fmaf(xv.w, v3.x, ax); ay = fmaf(xv.w, v3.y, ay);
        az = fmaf(xv.w, v3.z, az); aw = fmaf(xv.w, v3.w, aw);
        s += (xv.x + xv.y) + (xv.z + xv.w);
    }

    float* gTh = g_T + (size_t)half * (M_TOTAL * NB * RANK);
    *((float4*)(gTh + (size_t)(row0 + mm) * (NB * RANK) + i * RANK + rg * 4)) =
        make_float4(ax, ay, az, aw);

    if (rg == 0)
        g_rsp[(size_t)(row0 + mm) * (NB * 2) + i * 2 + half] = s;
}

// ---------------- Kernel B: out_block(o) = Z_o @ U[o] + (rowsum+1)*bias ----------------
#define ROWS_B  32
#define TSTRIDE 264   // 256 + 8 pad
#define ZSTRIDE 20    // 16 + 4 pad

__global__ void __launch_bounds__(256)
kernelB(const float* __restrict__ S, const float* __restrict__ U,
        const float* __restrict__ bias, float* __restrict__ out)
{
    __shared__ float Ts[ROWS_B * TSTRIDE];   // 33.8 KB
    __shared__ float Zs[ROWS_B * ZSTRIDE];   // 2.6 KB
    __shared__ float rs[ROWS_B];

    const int o    = blockIdx.x;             // output block 0..15
    const int row0 = blockIdx.y * ROWS_B;
    const int tid  = threadIdx.x;

    // Prefetch U column q=tid and bias (DRAM/L2 latency overlaps smem fill + sync)
    float u[16];
    const float* Ub = U + (size_t)o * (RANK * BLK);
    #pragma unroll
    for (int r = 0; r < 16; ++r) u[r] = Ub[r * 256 + tid];
    const float bq = bias[o * 256 + tid];

    // Load T rows (sum the two split-K halves)
    const float4* gT4a = (const float4*)g_T;
    const float4* gT4b = (const float4*)(g_T + (size_t)(M_TOTAL * NB * RANK));
    #pragma unroll
    for (int idx = tid; idx < ROWS_B * 64; idx += 256) {
        int m  = idx >> 6;
        int c4 = idx & 63;
        size_t gi = (size_t)(row0 + m) * 64 + c4;
        float4 a = gT4a[gi];
        float4 b = gT4b[gi];
        a.x += b.x; a.y += b.y; a.z += b.z; a.w += b.w;
        ((float4*)(Ts + m * TSTRIDE))[c4] = a;
    }
    // rowsum (fold +1 of the bias identity trick)
    if (tid < ROWS_B) {
        const float4* rp = (const float4*)(g_rsp + (size_t)(row0 + tid) * (NB * 2));
        float s = 1.0f;
        #pragma unroll
        for (int c = 0; c < 8; ++c) {
            float4 v = rp[c];
            s += (v.x + v.y) + (v.z + v.w);
        }
        rs[tid] = s;
    }
    __syncthreads();

    // Z[m][r] = sum_i T[m][i][r] * S[o][i][r]   (2 entries per thread)
    {
        const int zm = tid >> 3;       // row 0..31
        const int zr = tid & 7;        // r and r+8
        const float* Trow = Ts + zm * TSTRIDE;
        const float* Sb   = S + o * (NB * RANK);
        float z0 = 0.f, z1 = 0.f;
        #pragma unroll
        for (int i = 0; i < NB; ++i) {
            z0 = fmaf(Trow[i * 16 + zr],     __ldg(Sb + i * 16 + zr),     z0);
            z1 = fmaf(Trow[i * 16 + zr + 8], __ldg(Sb + i * 16 + zr + 8), z1);
        }
        Zs[zm * ZSTRIDE + zr]     = z0;
        Zs[zm * ZSTRIDE + zr + 8] = z1;
    }
    __syncthreads();

    // out[row0+m][o*256+tid] = sum_r Zs[m][r]*u[r] + rs[m]*bq
    const size_t ob = (size_t)row0 * OUT_DIM + o * 256 + tid;
    #pragma unroll 4
    for (int m = 0; m < ROWS_B; ++m) {
        const float4* zp = (const float4*)(Zs + m * ZSTRIDE);
        float4 za = zp[0], zb = zp[1], zc = zp[2], zd = zp[3];
        float acc = rs[m] * bq;
        acc = fmaf(za.x, u[0],  acc); acc = fmaf(za.y, u[1],  acc);
        acc = fmaf(za.z, u[2],  acc); acc = fmaf(za.w, u[3],  acc);
        acc = fmaf(zb.x, u[4],  acc); acc = fmaf(zb.y, u[5],  acc);
        acc = fmaf(zb.z, u[6],  acc); acc = fmaf(zb.w, u[7],  acc);
        acc = fmaf(zc.x, u[8],  acc); acc = fmaf(zc.y, u[9],  acc);
        acc = fmaf(zc.z, u[10], acc); acc = fmaf(zc.w, u[11], acc);
        acc = fmaf(zd.x, u[12], acc); acc = fmaf(zd.y, u[13], acc);
        acc = fmaf(zd.z, u[14], acc); acc = fmaf(zd.w, u[15], acc);
        out[ob + (size_t)m * OUT_DIM] = acc;
    }
}

extern "C" void kernel_launch(void* const* d_in, const int* in_sizes, int n_in,
                              void* d_out, int out_size)
{
    const float* x    = (const float*)d_in[0];
    const float* S    = (const float*)d_in[1];
    const float* U    = (const float*)d_in[2];
    const float* Vt   = (const float*)d_in[3];
    const float* bias = (const float*)d_in[4];
    float* out = (float*)d_out;

    kernelA<<<dim3(NB * 2, M_TOTAL / ROWS_A), 256>>>(x, Vt);
    kernelB<<<dim3(NB, M_TOTAL / ROWS_B), 256>>>(S, U, bias, out);
}

// round 3
// speedup vs baseline: 1.2974x; 1.1741x over previous
#include <cuda_runtime.h>

#define M_TOTAL 2048
#define IN_DIM  4096
#define OUT_DIM 4096
#define NB      16     // blocks per dim
#define RANK    16
#define BLK     256
#define NQ      4      // split-K quarters in kernelA
#define KA      64     // p's per quarter

// Scratch (__device__ globals per allocation rules)
__device__ float g_T[NQ * M_TOTAL * NB * RANK];   // [qt][m][i][r]  8 MB
__device__ float g_Z[NB * M_TOTAL * RANK];        // [o][m][r]      2 MB
__device__ float g_rsp[M_TOTAL * NB * NQ];        // [m][i*4+qt]

// ================= Kernel A: T_qt[m,i,r] = sum_{p in quarter} x*Vt =================
#define ROWS_A  128
#define XSTR    68     // 64 + 4 pad (floats); 68 mod 32 = 4 -> conflict-free

__global__ void __launch_bounds__(256)
kernelA(const float* __restrict__ x, const float* __restrict__ Vt)
{
    __shared__ float xs[ROWS_A * XSTR];    // 34.8 KB
    __shared__ float vts[KA * RANK];       // 4 KB

    const int ib   = blockIdx.x >> 2;      // input block 0..15
    const int qt   = blockIdx.x & 3;       // quarter 0..3
    const int row0 = blockIdx.y * ROWS_A;
    const int tid  = threadIdx.x;

    // Vt quarter: 64 p x 16 r = 256 float4
    ((float4*)vts)[tid] = ((const float4*)(Vt + (size_t)ib * (BLK * RANK) + qt * (KA * RANK)))[tid];

    // x tile: 128 rows x 64 cols
    const float4* xg4 = (const float4*)x;
    #pragma unroll
    for (int idx = tid; idx < ROWS_A * 16; idx += 256) {
        int m  = idx >> 4;
        int c4 = idx & 15;
        ((float4*)(xs + m * XSTR))[c4] =
            xg4[(size_t)(row0 + m) * (IN_DIM / 4) + ib * 64 + qt * 16 + c4];
    }
    __syncthreads();

    const int mg = tid >> 2;     // 0..63 -> rows mg and mg+64
    const int rg = tid & 3;      // r-quad
    const float4* xa4 = (const float4*)(xs + mg * XSTR);
    const float4* xb4 = (const float4*)(xs + (mg + 64) * XSTR);
    const float4* vt4 = (const float4*)vts;

    float a0x=0.f,a0y=0.f,a0z=0.f,a0w=0.f;
    float a1x=0.f,a1y=0.f,a1z=0.f,a1w=0.f;
    #pragma unroll 4
    for (int p4 = 0; p4 < 16; ++p4) {
        float4 x0 = xa4[p4];
        float4 x1 = xb4[p4];
        float4 v;
        v = vt4[16*p4 + rg];
        a0x=fmaf(x0.x,v.x,a0x); a0y=fmaf(x0.x,v.y,a0y); a0z=fmaf(x0.x,v.z,a0z); a0w=fmaf(x0.x,v.w,a0w);
        a1x=fmaf(x1.x,v.x,a1x); a1y=fmaf(x1.x,v.y,a1y); a1z=fmaf(x1.x,v.z,a1z); a1w=fmaf(x1.x,v.w,a1w);
        v = vt4[16*p4 + 4 + rg];
        a0x=fmaf(x0.y,v.x,a0x); a0y=fmaf(x0.y,v.y,a0y); a0z=fmaf(x0.y,v.z,a0z); a0w=fmaf(x0.y,v.w,a0w);
        a1x=fmaf(x1.y,v.x,a1x); a1y=fmaf(x1.y,v.y,a1y); a1z=fmaf(x1.y,v.z,a1z); a1w=fmaf(x1.y,v.w,a1w);
        v = vt4[16*p4 + 8 + rg];
        a0x=fmaf(x0.z,v.x,a0x); a0y=fmaf(x0.z,v.y,a0y); a0z=fmaf(x0.z,v.z,a0z); a0w=fmaf(x0.z,v.w,a0w);
        a1x=fmaf(x1.z,v.x,a1x); a1y=fmaf(x1.z,v.y,a1y); a1z=fmaf(x1.z,v.z,a1z); a1w=fmaf(x1.z,v.w,a1w);
        v = vt4[16*p4 + 12 + rg];
        a0x=fmaf(x0.w,v.x,a0x); a0y=fmaf(x0.w,v.y,a0y); a0z=fmaf(x0.w,v.z,a0z); a0w=fmaf(x0.w,v.w,a0w);
        a1x=fmaf(x1.w,v.x,a1x); a1y=fmaf(x1.w,v.y,a1y); a1z=fmaf(x1.w,v.z,a1z); a1w=fmaf(x1.w,v.w,a1w);
    }

    float* gTq = g_T + (size_t)qt * (M_TOTAL * NB * RANK);
    *((float4*)(gTq + (size_t)(row0 + mg)      * (NB*RANK) + ib*RANK + rg*4)) = make_float4(a0x,a0y,a0z,a0w);
    *((float4*)(gTq + (size_t)(row0 + mg + 64) * (NB*RANK) + ib*RANK + rg*4)) = make_float4(a1x,a1y,a1z,a1w);

    // rowsum partials (xs unchanged since sync; no extra barrier needed)
    if (tid < ROWS_A) {
        const float4* xr = (const float4*)(xs + tid * XSTR);
        float s = 0.f;
        #pragma unroll
        for (int c4 = 0; c4 < 16; ++c4) {
            float4 v = xr[c4];
            s += (v.x + v.y) + (v.z + v.w);
        }
        g_rsp[(size_t)(row0 + tid) * (NB*NQ) + ib*NQ + qt] = s;
    }
}

// ================= Kernel Z: Z[o][m][r] = sum_i T[m,i,r]*S[o,i,r] =================
#define ROWS_Z  16
#define TSTR    272    // 256 + 16 pad; 272 mod 32 = 16 -> conflict-free for 2 rows/warp

__global__ void __launch_bounds__(256)
kernelZ(const float* __restrict__ S)
{
    __shared__ float Ts[ROWS_Z * TSTR];    // 17.4 KB
    __shared__ float Ss[NB * NB * RANK];   // 16 KB (all of S)

    const int row0 = blockIdx.x * ROWS_Z;
    const int tid  = threadIdx.x;

    // All of S
    #pragma unroll
    for (int i = tid; i < 1024; i += 256) ((float4*)Ss)[i] = ((const float4*)S)[i];

    // T rows: sum 4 split-K quarters
    const float4* gT4 = (const float4*)g_T;
    #pragma unroll
    for (int idx = tid; idx < ROWS_Z * 64; idx += 256) {
        int m  = idx >> 6;
        int c4 = idx & 63;
        size_t gi = (size_t)(row0 + m) * 64 + c4;
        float4 a = gT4[gi];
        float4 b = gT4[gi + (size_t)1*(M_TOTAL*64)];
        float4 c = gT4[gi + (size_t)2*(M_TOTAL*64)];
        float4 d = gT4[gi + (size_t)3*(M_TOTAL*64)];
        a.x += b.x + c.x + d.x; a.y += b.y + c.y + d.y;
        a.z += b.z + c.z + d.z; a.w += b.w + c.w + d.w;
        ((float4*)(Ts + m * TSTR))[c4] = a;
    }
    __syncthreads();

    const int m = tid >> 4;      // 0..15
    const int r = tid & 15;

    float t[NB];
    #pragma unroll
    for (int i = 0; i < NB; ++i) t[i] = Ts[m * TSTR + i * 16 + r];

    #pragma unroll 4
    for (int o = 0; o < NB; ++o) {
        float z = 0.f;
        #pragma unroll
        for (int i = 0; i < NB; ++i) z = fmaf(t[i], Ss[o * 256 + i * 16 + r], z);
        g_Z[((size_t)o * M_TOTAL + row0 + m) * RANK + r] = z;
    }
}

// ================= Kernel B: out = Z @ U + (1+rowsum)*bias =================
#define ROWS_B  32
#define ZSTR    36     // 32 + 4 pad; 4*rq + m pattern -> conflict-free-ish

__global__ void __launch_bounds__(256)
kernelB(const float* __restrict__ U, const float* __restrict__ bias,
        float* __restrict__ out)
{
    __shared__ float Us[RANK * BLK];       // 16 KB
    __shared__ float Zt[RANK * ZSTR];      // 2.3 KB  (transposed: [r][m])
    __shared__ float rs[ROWS_B];

    const int o    = blockIdx.x;           // output block 0..15
    const int row0 = blockIdx.y * ROWS_B;
    const int tid  = threadIdx.x;

    // U block (flat copy, 1024 float4)
    const float4* Ug4 = (const float4*)(U + (size_t)o * (RANK * BLK));
    #pragma unroll
    for (int i = tid; i < 1024; i += 256) ((float4*)Us)[i] = Ug4[i];

    // Z slice, transposed into Zt[r][m]
    if (tid < 128) {
        int m  = tid >> 2;
        int rq = tid & 3;
        float4 z = ((const float4*)g_Z)[((size_t)o * M_TOTAL + row0 + m) * 4 + rq];
        Zt[(rq*4 + 0) * ZSTR + m] = z.x;
        Zt[(rq*4 + 1) * ZSTR + m] = z.y;
        Zt[(rq*4 + 2) * ZSTR + m] = z.z;
        Zt[(rq*4 + 3) * ZSTR + m] = z.w;
    }
    // rowsums: 1 + sum of 64 partials
    if (tid >= 128 && tid < 128 + ROWS_B) {
        int m = tid - 128;
        const float4* rp = (const float4*)(g_rsp + (size_t)(row0 + m) * (NB*NQ));
        float s = 1.0f;
        #pragma unroll
        for (int c = 0; c < 16; ++c) {
            float4 v = rp[c];
            s += (v.x + v.y) + (v.z + v.w);
        }
        rs[m] = s;
    }
    __syncthreads();

    const int mg = tid >> 5;        // 0..7 -> rows mg*4..mg*4+3
    const int qg = tid & 31;        // q = qg*4 and 128+qg*4
    const int m0 = mg * 4;

    // bias fragments + rowsum scalars
    const float4* b4 = (const float4*)bias;
    float4 ba = b4[o * 64 + qg];
    float4 bb = b4[o * 64 + 32 + qg];
    float r0 = rs[m0], r1 = rs[m0+1], r2 = rs[m0+2], r3 = rs[m0+3];

    // acc[m][2 float4] init with rs*bias
    float4 A0a, A0b, A1a, A1b, A2a, A2b, A3a, A3b;
    A0a.x=r0*ba.x; A0a.y=r0*ba.y; A0a.z=r0*ba.z; A0a.w=r0*ba.w;
    A0b.x=r0*bb.x; A0b.y=r0*bb.y; A0b.z=r0*bb.z; A0b.w=r0*bb.w;
    A1a.x=r1*ba.x; A1a.y=r1*ba.y; A1a.z=r1*ba.z; A1a.w=r1*ba.w;
    A1b.x=r1*bb.x; A1b.y=r1*bb.y; A1b.z=r1*bb.z; A1b.w=r1*bb.w;
    A2a.x=r2*ba.x; A2a.y=r2*ba.y; A2a.z=r2*ba.z; A2a.w=r2*ba.w;
    A2b.x=r2*bb.x; A2b.y=r2*bb.y; A2b.z=r2*bb.z; A2b.w=r2*bb.w;
    A3a.x=r3*ba.x; A3a.y=r3*ba.y; A3a.z=r3*ba.z; A3a.w=r3*ba.w;
    A3b.x=r3*bb.x; A3b.y=r3*bb.y; A3b.z=r3*bb.z; A3b.w=r3*bb.w;

    const float4* Us4 = (const float4*)Us;
    #pragma unroll
    for (int r = 0; r < RANK; ++r) {
        float4 z  = *((const float4*)(Zt + r * ZSTR + m0));   // broadcast in warp
        float4 ua = Us4[r * 64 + qg];
        float4 ub = Us4[r * 64 + 32 + qg];
        A0a.x=fmaf(z.x,ua.x,A0a.x); A0a.y=fmaf(z.x,ua.y,A0a.y); A0a.z=fmaf(z.x,ua.z,A0a.z); A0a.w=fmaf(z.x,ua.w,A0a.w);
        A0b.x=fmaf(z.x,ub.x,A0b.x); A0b.y=fmaf(z.x,ub.y,A0b.y); A0b.z=fmaf(z.x,ub.z,A0b.z); A0b.w=fmaf(z.x,ub.w,A0b.w);
        A1a.x=fmaf(z.y,ua.x,A1a.x); A1a.y=fmaf(z.y,ua.y,A1a.y); A1a.z=fmaf(z.y,ua.z,A1a.z); A1a.w=fmaf(z.y,ua.w,A1a.w);
        A1b.x=fmaf(z.y,ub.x,A1b.x); A1b.y=fmaf(z.y,ub.y,A1b.y); A1b.z=fmaf(z.y,ub.z,A1b.z); A1b.w=fmaf(z.y,ub.w,A1b.w);
        A2a.x=fmaf(z.z,ua.x,A2a.x); A2a.y=fmaf(z.z,ua.y,A2a.y); A2a.z=fmaf(z.z,ua.z,A2a.z); A2a.w=fmaf(z.z,ua.w,A2a.w);
        A2b.x=fmaf(z.z,ub.x,A2b.x); A2b.y=fmaf(z.z,ub.y,A2b.y); A2b.z=fmaf(z.z,ub.z,A2b.z); A2b.w=fmaf(z.z,ub.w,A2b.w);
        A3a.x=fmaf(z.w,ua.x,A3a.x); A3a.y=fmaf(z.w,ua.y,A3a.y); A3a.z=fmaf(z.w,ua.z,A3a.z); A3a.w=fmaf(z.w,ua.w,A3a.w);
        A3b.x=fmaf(z.w,ub.x,A3b.x); A3b.y=fmaf(z.w,ub.y,A3b.y); A3b.z=fmaf(z.w,ub.z,A3b.z); A3b.w=fmaf(z.w,ub.w,A3b.w);
    }

    float4* out4 = (float4*)out;
    size_t ob = (size_t)(row0 + m0) * (OUT_DIM/4) + o * 64 + qg;
    out4[ob]                         = A0a;  out4[ob + 32]                    = A0b;
    out4[ob + (OUT_DIM/4)]           = A1a;  out4[ob + (OUT_DIM/4) + 32]      = A1b;
    out4[ob + 2*(OUT_DIM/4)]         = A2a;  out4[ob + 2*(OUT_DIM/4) + 32]    = A2b;
    out4[ob + 3*(OUT_DIM/4)]         = A3a;  out4[ob + 3*(OUT_DIM/4) + 32]    = A3b;
}

extern "C" void kernel_launch(void* const* d_in, const int* in_sizes, int n_in,
                              void* d_out, int out_size)
{
    const float* x    = (const float*)d_in[0];
    const float* S    = (const float*)d_in[1];
    const float* U    = (const float*)d_in[2];
    const float* Vt   = (const float*)d_in[3];
    const float* bias = (const float*)d_in[4];
    float* out = (float*)d_out;

    kernelA<<<dim3(NB * NQ, M_TOTAL / ROWS_A), 256>>>(x, Vt);
    kernelZ<<<M_TOTAL / ROWS_Z, 256>>>(S);
    kernelB<<<dim3(NB, M_TOTAL / ROWS_B), 256>>>(U, bias, out);
}

// round 4
// speedup vs baseline: 1.3513x; 1.0415x over previous
#include <cuda_runtime.h>

#define M_TOTAL 2048
#define IN_DIM  4096
#define OUT_DIM 4096
#define NB      16
#define RANK    16
#define BLK     256
#define NQ      4      // split-K quarters in kernelA
#define KA      64     // p's per quarter

// Scratch (__device__ globals per allocation rules)
__device__ float g_T[NQ * M_TOTAL * NB * RANK];   // [qt][m][i][r]  8 MB
__device__ float g_Z[NB * M_TOTAL * RANK];        // [o][m][r]      2 MB
__device__ float g_rsp[M_TOTAL * NB * NQ];        // [m][i*4+qt]

// ---------- f32x2 packed helpers (Blackwell FFMA2 path) ----------
typedef unsigned long long u64;

__device__ __forceinline__ u64 pack2(float lo, float hi) {
    u64 r; asm("mov.b64 %0, {%1, %2};" : "=l"(r) : "f"(lo), "f"(hi)); return r;
}
__device__ __forceinline__ void unpack2(u64 p, float& lo, float& hi) {
    asm("mov.b64 {%0, %1}, %2;" : "=f"(lo), "=f"(hi) : "l"(p));
}
__device__ __forceinline__ void ffma2(u64& d, u64 a, u64 b) {
    asm("fma.rn.f32x2 %0, %1, %2, %0;" : "+l"(d) : "l"(a), "l"(b));
}
__device__ __forceinline__ void fadd2(u64& d, u64 a) {
    asm("add.rn.f32x2 %0, %0, %1;" : "+l"(d) : "l"(a));
}

// ================= Kernel A: T_qt[m,i,r] = sum_{p in quarter} x*Vt =================
#define ROWS_A  256
#define XSTR    68     // 64 + 4 pad floats; conflict-free

__global__ void __launch_bounds__(256)
kernelA(const float* __restrict__ x, const float* __restrict__ Vt)
{
    extern __shared__ float sm[];
    float* xs  = sm;                      // ROWS_A * XSTR = 69,632 B
    float* vts = sm + ROWS_A * XSTR;      // KA*RANK = 4 KB

    const int ib   = blockIdx.x >> 2;
    const int qt   = blockIdx.x & 3;
    const int row0 = blockIdx.y * ROWS_A;
    const int tid  = threadIdx.x;

    // Vt quarter: 64p x 16r = 256 float4
    ((float4*)vts)[tid] =
        ((const float4*)(Vt + (size_t)ib * (BLK * RANK) + qt * (KA * RANK)))[tid];

    // x tile: 256 rows x 64 cols (16 float4 per thread)
    const float4* xg4 = (const float4*)x;
    #pragma unroll
    for (int idx = tid; idx < ROWS_A * 16; idx += 256) {
        int m  = idx >> 4;
        int c4 = idx & 15;
        ((float4*)(xs + m * XSTR))[c4] =
            xg4[(size_t)(row0 + m) * (IN_DIM / 4) + ib * 64 + qt * 16 + c4];
    }
    __syncthreads();

    const int mg = tid >> 2;     // 0..63 -> rows mg, mg+64, mg+128, mg+192
    const int rg = tid & 3;      // r-quad

    ulonglong2 acc[4];
    #pragma unroll
    for (int j = 0; j < 4; ++j) { acc[j].x = 0ULL; acc[j].y = 0ULL; }

    const ulonglong2* vt2 = (const ulonglong2*)vts;   // [p][rquad] as (r0,r1),(r2,r3)

    #pragma unroll 4
    for (int p4 = 0; p4 < 16; ++p4) {
        // Vt pairs for p = 4*p4 + {0,1,2,3}, this thread's r-quad
        ulonglong2 v0 = vt2[16 * p4 + rg];
        ulonglong2 v1 = vt2[16 * p4 + 4 + rg];
        ulonglong2 v2 = vt2[16 * p4 + 8 + rg];
        ulonglong2 v3 = vt2[16 * p4 + 12 + rg];
        #pragma unroll
        for (int j = 0; j < 4; ++j) {
            ulonglong2 xv = *(const ulonglong2*)(xs + (mg + 64 * j) * XSTR + p4 * 4);
            float x0, x1, x2, x3;
            unpack2(xv.x, x0, x1);
            unpack2(xv.y, x2, x3);
            u64 b0 = pack2(x0, x0), b1 = pack2(x1, x1);
            u64 b2 = pack2(x2, x2), b3 = pack2(x3, x3);
            ffma2(acc[j].x, b0, v0.x); ffma2(acc[j].y, b0, v0.y);
            ffma2(acc[j].x, b1, v1.x); ffma2(acc[j].y, b1, v1.y);
            ffma2(acc[j].x, b2, v2.x); ffma2(acc[j].y, b2, v2.y);
            ffma2(acc[j].x, b3, v3.x); ffma2(acc[j].y, b3, v3.y);
        }
    }

    float* gTq = g_T + (size_t)qt * (M_TOTAL * NB * RANK);
    #pragma unroll
    for (int j = 0; j < 4; ++j) {
        *((ulonglong2*)(gTq + (size_t)(row0 + mg + 64 * j) * (NB * RANK)
                            + ib * RANK + rg * 4)) = acc[j];
    }

    // rowsum partials: one thread per row (xs unchanged since sync)
    {
        const ulonglong2* xr = (const ulonglong2*)(xs + tid * XSTR);
        u64 s0 = 0ULL, s1 = 0ULL;
        #pragma unroll
        for (int c = 0; c < 16; ++c) {
            ulonglong2 v = xr[c];
            fadd2(s0, v.x);
            fadd2(s1, v.y);
        }
        float a, b, c, d;
        unpack2(s0, a, b);
        unpack2(s1, c, d);
        g_rsp[(size_t)(row0 + tid) * (NB * NQ) + ib * NQ + qt] = (a + b) + (c + d);
    }
}

// ================= Kernel Z: Z[o][m][r] = sum_i T[m,i,r]*S[o,i,r] =================
#define ROWS_Z  16
#define TSTR    272

__global__ void __launch_bounds__(256)
kernelZ(const float* __restrict__ S)
{
    __shared__ float Ts[ROWS_Z * TSTR];
    __shared__ float Ss[NB * NB * RANK];

    const int row0 = blockIdx.x * ROWS_Z;
    const int tid  = threadIdx.x;

    #pragma unroll
    for (int i = tid; i < 1024; i += 256) ((float4*)Ss)[i] = ((const float4*)S)[i];

    const float4* gT4 = (const float4*)g_T;
    #pragma unroll
    for (int idx = tid; idx < ROWS_Z * 64; idx += 256) {
        int m  = idx >> 6;
        int c4 = idx & 63;
        size_t gi = (size_t)(row0 + m) * 64 + c4;
        float4 a = gT4[gi];
        float4 b = gT4[gi + (size_t)1 * (M_TOTAL * 64)];
        float4 c = gT4[gi + (size_t)2 * (M_TOTAL * 64)];
        float4 d = gT4[gi + (size_t)3 * (M_TOTAL * 64)];
        a.x += b.x + c.x + d.x; a.y += b.y + c.y + d.y;
        a.z += b.z + c.z + d.z; a.w += b.w + c.w + d.w;
        ((float4*)(Ts + m * TSTR))[c4] = a;
    }
    __syncthreads();

    const int m = tid >> 4;
    const int r = tid & 15;

    float t[NB];
    #pragma unroll
    for (int i = 0; i < NB; ++i) t[i] = Ts[m * TSTR + i * 16 + r];

    #pragma unroll 4
    for (int o = 0; o < NB; ++o) {
        float z = 0.f;
        #pragma unroll
        for (int i = 0; i < NB; ++i) z = fmaf(t[i], Ss[o * 256 + i * 16 + r], z);
        g_Z[((size_t)o * M_TOTAL + row0 + m) * RANK + r] = z;
    }
}

// ================= Kernel B: out = Z @ U + (1+rowsum)*bias =================
#define ROWS_B  32
#define ZSTR    36

__global__ void __launch_bounds__(256)
kernelB(const float* __restrict__ U, const float* __restrict__ bias,
        float* __restrict__ out)
{
    __shared__ float Us[RANK * BLK];       // 16 KB
    __shared__ float Zt[RANK * ZSTR];      // transposed: [r][m]
    __shared__ float rs[ROWS_B];

    const int o    = blockIdx.x;
    const int row0 = blockIdx.y * ROWS_B;
    const int tid  = threadIdx.x;

    const float4* Ug4 = (const float4*)(U + (size_t)o * (RANK * BLK));
    #pragma unroll
    for (int i = tid; i < 1024; i += 256) ((float4*)Us)[i] = Ug4[i];

    if (tid < 128) {
        int m  = tid >> 2;
        int rq = tid & 3;
        float4 z = ((const float4*)g_Z)[((size_t)o * M_TOTAL + row0 + m) * 4 + rq];
        Zt[(rq * 4 + 0) * ZSTR + m] = z.x;
        Zt[(rq * 4 + 1) * ZSTR + m] = z.y;
        Zt[(rq * 4 + 2) * ZSTR + m] = z.z;
        Zt[(rq * 4 + 3) * ZSTR + m] = z.w;
    }
    if (tid >= 128 && tid < 128 + ROWS_B) {
        int m = tid - 128;
        const float4* rp = (const float4*)(g_rsp + (size_t)(row0 + m) * (NB * NQ));
        float s = 1.0f;
        #pragma unroll
        for (int c = 0; c < 16; ++c) {
            float4 v = rp[c];
            s += (v.x + v.y) + (v.z + v.w);
        }
        rs[m] = s;
    }
    __syncthreads();

    const int mg = tid >> 5;        // 0..7 -> rows m0..m0+3
    const int qg = tid & 31;        // q = qg*4 and 128+qg*4
    const int m0 = mg * 4;

    const float4* b4 = (const float4*)bias;
    float4 ba = b4[o * 64 + qg];
    float4 bb = b4[o * 64 + 32 + qg];

    ulonglong2 Aa[4], Ab[4];
    #pragma unroll
    for (int j = 0; j < 4; ++j) {
        float r = rs[m0 + j];
        Aa[j].x = pack2(r * ba.x, r * ba.y);
        Aa[j].y = pack2(r * ba.z, r * ba.w);
        Ab[j].x = pack2(r * bb.x, r * bb.y);
        Ab[j].y = pack2(r * bb.z, r * bb.w);
    }

    const float* Usf = Us;
    #pragma unroll
    for (int r = 0; r < RANK; ++r) {
        ulonglong2 zp = *(const ulonglong2*)(Zt + r * ZSTR + m0);
        float z0, z1, z2, z3;
        unpack2(zp.x, z0, z1);
        unpack2(zp.y, z2, z3);
        u64 q0 = pack2(z0, z0), q1 = pack2(z1, z1);
        u64 q2 = pack2(z2, z2), q3 = pack2(z3, z3);
        ulonglong2 ua = *(const ulonglong2*)(Usf + r * 256 + qg * 4);
        ulonglong2 ub = *(const ulonglong2*)(Usf + r * 256 + 128 + qg * 4);
        ffma2(Aa[0].x, q0, ua.x); ffma2(Aa[0].y, q0, ua.y);
        ffma2(Ab[0].x, q0, ub.x); ffma2(Ab[0].y, q0, ub.y);
        ffma2(Aa[1].x, q1, ua.x); ffma2(Aa[1].y, q1, ua.y);
        ffma2(Ab[1].x, q1, ub.x); ffma2(Ab[1].y, q1, ub.y);
        ffma2(Aa[2].x, q2, ua.x); ffma2(Aa[2].y, q2, ua.y);
        ffma2(Ab[2].x, q2, ub.x); ffma2(Ab[2].y, q2, ub.y);
        ffma2(Aa[3].x, q3, ua.x); ffma2(Aa[3].y, q3, ua.y);
        ffma2(Ab[3].x, q3, ub.x); ffma2(Ab[3].y, q3, ub.y);
    }

    size_t ob = (size_t)(row0 + m0) * OUT_DIM + o * 256 + qg * 4;
    #pragma unroll
    for (int j = 0; j < 4; ++j) {
        *(ulonglong2*)(out + ob + (size_t)j * OUT_DIM)       = Aa[j];
        *(ulonglong2*)(out + ob + (size_t)j * OUT_DIM + 128) = Ab[j];
    }
}

extern "C" void kernel_launch(void* const* d_in, const int* in_sizes, int n_in,
                              void* d_out, int out_size)
{
    const float* x    = (const float*)d_in[0];
    const float* S    = (const float*)d_in[1];
    const float* U    = (const float*)d_in[2];
    const float* Vt   = (const float*)d_in[3];
    const float* bias = (const float*)d_in[4];
    float* out = (float*)d_out;

    const int smA = (ROWS_A * XSTR + KA * RANK) * (int)sizeof(float);  // 73,728 B
    cudaFuncSetAttribute(kernelA, cudaFuncAttributeMaxDynamicSharedMemorySize, smA);

    kernelA<<<dim3(NB * NQ, M_TOTAL / ROWS_A), 256, smA>>>(x, Vt);
    kernelZ<<<M_TOTAL / ROWS_Z, 256>>>(S);
    kernelB<<<dim3(NB, M_TOTAL / ROWS_B), 256>>>(U, bias, out);
}